// round 16
// baseline (speedup 1.0000x reference)
#include <cuda_runtime.h>
#include <cuda_fp16.h>

#define RW 192
#define TW 182
#define TH 24          // output rows per tile
#define NP 12          // row pairs per tile
#define RH 34          // TH + 10 input rows
#define PITCH 772      // u32 words per pair-row: 192*4 + 4; 772%32==4 -> conflict-free
#define SMEM_WORDS (NP * PITCH + 160)   // pad covers phase-C tail overreads
#define NTHREADS 192
#define IMG_W 512
#define IMG_H 512
#define PLANES 96
#define YBLOCKS 22     // ceil(512/24)
#define NBLOCKS (3 * YBLOCKS * 96)
#define NPIX 25165824.0f

static constexpr float C1V = 0.0001f;
static constexpr float C2V = 0.0009f;

// fp16 bit patterns of the Gaussian(sigma=1.5,k=11) weights (== cvt.rn.f16.f32,
// validated bit-exact in R12).
__host__ __device__ constexpr unsigned hw(int k) {
    return (k == 0 || k == 10) ? 0x1436u
         : (k == 1 || k == 9)  ? 0x1FC8u
         : (k == 2 || k == 8)  ? 0x289Cu
         : (k == 3 || k == 7)  ? 0x2F00u
         : (k == 4 || k == 6)  ? 0x32D1u
         : (k == 5)            ? 0x3442u
         : 0u;
}
__host__ __device__ constexpr unsigned wk2(int k) { return hw(k) | (hw(k - 1) << 16); }
__host__ __device__ constexpr unsigned wb2(int k) { return hw(k) | (hw(k) << 16); }

__device__ float g_accum;
__device__ unsigned int g_count;

__device__ __forceinline__ unsigned hfma2u(unsigned a, unsigned b, unsigned c) {
    unsigned d; asm("fma.rn.f16x2 %0,%1,%2,%3;" : "=r"(d) : "r"(a), "r"(b), "r"(c)); return d;
}
__device__ __forceinline__ unsigned hmul2u(unsigned a, unsigned b) {
    unsigned d; asm("mul.rn.f16x2 %0,%1,%2;" : "=r"(d) : "r"(a), "r"(b)); return d;
}
__device__ __forceinline__ unsigned hadd2u(unsigned a, unsigned b) {
    unsigned d; asm("add.rn.f16x2 %0,%1,%2;" : "=r"(d) : "r"(a), "r"(b)); return d;
}
__device__ __forceinline__ unsigned hsub2u(unsigned a, unsigned b) {
    unsigned d; asm("sub.rn.f16x2 %0,%1,%2;" : "=r"(d) : "r"(a), "r"(b)); return d;
}
__device__ __forceinline__ unsigned bcast_h2(float f) {
    unsigned d; asm("cvt.rn.f16x2.f32 %0, %1, %1;" : "=r"(d) : "f"(f)); return d;
}
__device__ __forceinline__ float2 unpack_h2(unsigned u) {
    __half2 h = *reinterpret_cast<__half2*>(&u);
    return make_float2(__low2float(h), __high2float(h));
}

// Vertical blur on CENTERED inputs (ac = a-0.5; out-of-image -> -0.5).
// fp16 moments; lanes of each half2 = output rows (2p, 2p+1).
// Ring of 6: pairs p and p+6 are never simultaneously live.
template <bool YSAFE, bool XSAFE>
__device__ __forceinline__ void vblur(const float* __restrict__ p1,
                                      const float* __restrict__ p2,
                                      unsigned* __restrict__ vw,
                                      int y0, int gx, bool xok, int tx) {
    unsigned acc[6][4];

#pragma unroll
    for (int r = 0; r < RH; r++) {
        const int gy = y0 - 5 + r;
        float a, b;
        if (YSAFE && XSAFE) {
            const int idx = gy * IMG_W + gx;
            a = __ldg(p1 + idx) - 0.5f;
            b = __ldg(p2 + idx) - 0.5f;
        } else {
            a = -0.5f; b = -0.5f;
            const bool ok = (XSAFE || xok) && (YSAFE || ((gy >= 0) && (gy < IMG_H)));
            if (ok) {
                const int idx = gy * IMG_W + gx;
                a = __ldg(p1 + idx) - 0.5f;
                b = __ldg(p2 + idx) - 0.5f;
            }
        }
        unsigned pq[4];
        pq[0] = bcast_h2(a);
        pq[1] = bcast_h2(b);
        pq[2] = hfma2u(pq[0], pq[0], hmul2u(pq[1], pq[1]));  // ac^2+bc^2
        pq[3] = hmul2u(pq[0], pq[1]);                        // ac*bc

#pragma unroll
        for (int p = 0; p < NP; p++) {
            const int k = r - 2 * p;            // compile-time after unroll
            if (k >= 0 && k <= 11) {
                const int j = p % 6;
                if (k == 0) {
#pragma unroll
                    for (int q = 0; q < 4; q++)
                        acc[j][q] = hmul2u(pq[q], wk2(0));   // fresh pair (lane1 *0)
                } else {
#pragma unroll
                    for (int q = 0; q < 4; q++)
                        acc[j][q] = hfma2u(pq[q], wk2(k), acc[j][q]);
                }
            }
        }
        if (r >= 11 && ((r - 11) & 1) == 0) {
            const int p = (r - 11) >> 1;
            const int j = p % 6;
            uint4 w4 = make_uint4(acc[j][0], acc[j][1], acc[j][2], acc[j][3]);
            *reinterpret_cast<uint4*>(vw + p * PITCH + tx * 4) = w4;
        }
    }
}

__global__ void __launch_bounds__(NTHREADS, 6)
ssim_main(const float* __restrict__ img1, const float* __restrict__ img2,
          float* __restrict__ out) {
    extern __shared__ unsigned vw[];      // [NP][PITCH] + pad
    __shared__ float red[NTHREADS / 32];

    const int tx = threadIdx.x;
    const int plane = blockIdx.z;
    const int x0 = blockIdx.x * TW;
    const int y0 = blockIdx.y * TH;

    const float* __restrict__ p1 = img1 + (size_t)plane * (IMG_W * IMG_H);
    const float* __restrict__ p2 = img2 + (size_t)plane * (IMG_W * IMG_H);

    const int gx = x0 - 5 + tx;
    const bool xok = (gx >= 0) && (gx < IMG_W);
    const int xlim = (IMG_W - x0 < TW) ? (IMG_W - x0) : TW;

    // Dead-column skip: raw column tx feeds a kept output only if tx <= xlim+9.
    const bool bcol_live = (tx <= xlim + 9);

    // ---------- Phase B (Y/X-safe specialization; dead warps skip) ----------
    if (bcol_live) {
        const bool ysafe = (y0 >= 5) && (y0 + TH + 5 <= IMG_H);
        const bool xsafe = (blockIdx.x == 1);   // gx in [177,368] -> always in range
        if (ysafe) {
            if (xsafe) vblur<true , true >(p1, p2, vw, y0, gx, xok, tx);
            else       vblur<true , false>(p1, p2, vw, y0, gx, xok, tx);
        } else {
            if (xsafe) vblur<false, true >(p1, p2, vw, y0, gx, xok, tx);
            else       vblur<false, false>(p1, p2, vw, y0, gx, xok, tx);
        }
    }
    __syncthreads();

    // ---------- Phase C: horizontal blur + SSIM epilogue ----------
    // rp = tx % 12 (pair-row), seg = tx / 12 (0..15, 12 output columns each,
    // split in two 6-wide windows). Bank-checked: word-addr == 4*rp + 16*seg
    // (mod 32), distinct across every quarter-warp -> LDS.128 conflict-free.
    const int rp  = tx % 12;
    const int seg = tx / 12;
    // y-liveness (last y block only: rows >= 512 are padded garbage, excluded)
    const bool ylive = (y0 + 2 * rp) < IMG_H;

    // h2 constants for the pair-packed epilogue
    const unsigned HC1   = bcast_h2(C1V);
    const unsigned HC2   = bcast_h2(C2V);
    const unsigned HTWO  = bcast_h2(2.0f);
    const unsigned HHALF = bcast_h2(0.5f);
    const unsigned HQTR  = bcast_h2(0.25f);
    const unsigned HHC1  = bcast_h2(0.5f + C1V);

    float lsum = 0.f;

#pragma unroll
    for (int win = 0; win < 2; win++) {
        const int c0 = seg * 12 + win * 6;
        if (c0 < xlim && ylive) {
            unsigned acc[6][4];
            const unsigned* rowp = vw + rp * PITCH + c0 * 4;

#pragma unroll
            for (int i = 0; i < 16; i++) {
                // One LDS.128: 4 quantities x 2 rows of column c0+i. Tail
                // overreads stay inside the padded allocation and feed only
                // outputs discarded by the xout < xlim guard below.
                const uint4 w4 = *reinterpret_cast<const uint4*>(rowp + i * 4);
                unsigned pv[4] = {w4.x, w4.y, w4.z, w4.w};
#pragma unroll
                for (int xo = 0; xo < 6; xo++) {
                    const int k = i - xo;
                    if (k >= 0 && k <= 10) {
                        if (k == 0) {
#pragma unroll
                            for (int q = 0; q < 4; q++)
                                acc[xo][q] = hmul2u(pv[q], wb2(0));
                        } else {
#pragma unroll
                            for (int q = 0; q < 4; q++)
                                acc[xo][q] = hfma2u(pv[q], wb2(k < 6 ? k : 10 - k), acc[xo][q]);
                        }
                    }
                }
            }

#pragma unroll
            for (int xo = 0; xo < 6; xo++) {
                const int xout = c0 + xo;
                if (xout < xlim) {
                    const unsigned mu1c = acc[xo][0];
                    const unsigned mu2c = acc[xo][1];
                    const unsigned epc  = acc[xo][2];
                    const unsigned exc  = acc[xo][3];
                    const unsigned msumc = hfma2u(mu1c, mu1c, hmul2u(mu2c, mu2c));
                    const unsigned ssum  = hsub2u(epc, msumc);        // s1+s2
                    const unsigned m12c  = hmul2u(mu1c, mu2c);
                    const unsigned s12   = hsub2u(exc, m12c);
                    // de-center: u = mu1c+mu2c; m12 = m12c + u/2 + 1/4;
                    //            msum+C1 = msumc + u + (1/2+C1)
                    const unsigned u      = hadd2u(mu1c, mu2c);
                    const unsigned m12    = hadd2u(m12c, hfma2u(u, HHALF, HQTR));
                    const unsigned msumC1 = hadd2u(msumc, hadd2u(u, HHC1));
                    const unsigned numf1  = hfma2u(m12, HTWO, HC1);
                    const unsigned numf2  = hfma2u(s12, HTWO, HC2);
                    const unsigned num_h  = hmul2u(numf1, numf2);
                    const unsigned ssumC2 = hadd2u(ssum, HC2);
                    const unsigned den_h  = hmul2u(msumC1, ssumC2);
                    const float2 numf = unpack_h2(num_h);
                    const float2 denf = unpack_h2(den_h);
                    lsum += __fdividef(numf.x, denf.x);
                    lsum += __fdividef(numf.y, denf.y);
                }
            }
        }
    }

    // ---------- reduction: shuffle -> smem -> one atomic per block ----------
#pragma unroll
    for (int off = 16; off > 0; off >>= 1)
        lsum += __shfl_xor_sync(0xffffffffu, lsum, off);
    if ((tx & 31) == 0) red[tx >> 5] = lsum;
    __syncthreads();

    if (tx == 0) {
        float bsum = 0.f;
#pragma unroll
        for (int w = 0; w < NTHREADS / 32; w++) bsum += red[w];
        atomicAdd(&g_accum, bsum);
        __threadfence();
        const unsigned int old = atomicAdd(&g_count, 1u);
        if (old == NBLOCKS - 1) {
            __threadfence();
            const float total = *(volatile float*)&g_accum;
            out[0] = 1.0f - total * (1.0f / NPIX);
            *(volatile float*)&g_accum = 0.f;
            *(volatile unsigned int*)&g_count = 0u;
        }
    }
}

extern "C" void kernel_launch(void* const* d_in, const int* in_sizes, int n_in,
                              void* d_out, int out_size) {
    const float* img1 = (const float*)d_in[0];
    const float* img2 = (const float*)d_in[1];

    const int smem = SMEM_WORDS * (int)sizeof(unsigned);   // 37,696 B
    cudaFuncSetAttribute(ssim_main, cudaFuncAttributeMaxDynamicSharedMemorySize, smem);

    dim3 grid((IMG_W + TW - 1) / TW, YBLOCKS, PLANES);     // (3, 22, 96)
    ssim_main<<<grid, NTHREADS, smem>>>(img1, img2, (float*)d_out);
}

// round 17
// speedup vs baseline: 1.1090x; 1.1090x over previous
#include <cuda_runtime.h>
#include <cuda_fp16.h>

#define TH 16          // output rows per tile
#define NP 8           // row pairs per tile
#define RH 26          // TH + 10 input rows
#define SW 522         // smem columns: 5 + 512 + 5 (boundary constants)
#define PITCH 2092     // u32 words per pair-row: 522*4 + 4; 2092%32==12 -> conflict-free
#define SMEM_WORDS (NP * PITCH + 16)
#define NTHREADS 512
#define IMG_W 512
#define IMG_H 512
#define PLANES 96
#define NBLOCKS (32 * 96)
#define NPIX 25165824.0f

static constexpr float C1V = 0.0001f;
static constexpr float C2V = 0.0009f;

// fp16 bit patterns of the Gaussian(sigma=1.5,k=11) weights (== cvt.rn.f16.f32,
// validated bit-exact in R12).
__host__ __device__ constexpr unsigned hw(int k) {
    return (k == 0 || k == 10) ? 0x1436u
         : (k == 1 || k == 9)  ? 0x1FC8u
         : (k == 2 || k == 8)  ? 0x289Cu
         : (k == 3 || k == 7)  ? 0x2F00u
         : (k == 4 || k == 6)  ? 0x32D1u
         : (k == 5)            ? 0x3442u
         : 0u;
}
__host__ __device__ constexpr unsigned wk2(int k) { return hw(k) | (hw(k - 1) << 16); }
__host__ __device__ constexpr unsigned wb2(int k) { return hw(k) | (hw(k) << 16); }

// Boundary-column constants (vertical blur of centered out-of-image input):
// mu1c = mu2c = -0.5, s = 0.5, m = 0.25 as half2 bit patterns.
#define HMU_BC 0xB800B800u
#define HS_BC  0x38003800u
#define HM_BC  0x34003400u

__device__ float g_accum;
__device__ unsigned int g_count;

__device__ __forceinline__ unsigned hfma2u(unsigned a, unsigned b, unsigned c) {
    unsigned d; asm("fma.rn.f16x2 %0,%1,%2,%3;" : "=r"(d) : "r"(a), "r"(b), "r"(c)); return d;
}
__device__ __forceinline__ unsigned hmul2u(unsigned a, unsigned b) {
    unsigned d; asm("mul.rn.f16x2 %0,%1,%2;" : "=r"(d) : "r"(a), "r"(b)); return d;
}
__device__ __forceinline__ unsigned hadd2u(unsigned a, unsigned b) {
    unsigned d; asm("add.rn.f16x2 %0,%1,%2;" : "=r"(d) : "r"(a), "r"(b)); return d;
}
__device__ __forceinline__ unsigned hsub2u(unsigned a, unsigned b) {
    unsigned d; asm("sub.rn.f16x2 %0,%1,%2;" : "=r"(d) : "r"(a), "r"(b)); return d;
}
__device__ __forceinline__ unsigned bcast_h2(float f) {
    unsigned d; asm("cvt.rn.f16x2.f32 %0, %1, %1;" : "=r"(d) : "f"(f)); return d;
}
__device__ __forceinline__ float2 unpack_h2(unsigned u) {
    __half2 h = *reinterpret_cast<__half2*>(&u);
    return make_float2(__low2float(h), __high2float(h));
}

// Vertical blur on CENTERED inputs (ac = a-0.5; out-of-image rows -> -0.5).
// Column gx = tx is ALWAYS in-image (full-row tile): no x guards at all.
// fp16 moments; lanes of each half2 = output rows (2p, 2p+1).
template <bool YSAFE>
__device__ __forceinline__ void vblur(const float* __restrict__ p1,
                                      const float* __restrict__ p2,
                                      unsigned* __restrict__ vw,
                                      int y0, int tx) {
    unsigned acc[6][4];

#pragma unroll
    for (int r = 0; r < RH; r++) {
        const int gy = y0 - 5 + r;
        float a, b;
        if (YSAFE) {
            const int idx = gy * IMG_W + tx;
            a = __ldg(p1 + idx) - 0.5f;
            b = __ldg(p2 + idx) - 0.5f;
        } else {
            a = -0.5f; b = -0.5f;
            if (gy >= 0 && gy < IMG_H) {
                const int idx = gy * IMG_W + tx;
                a = __ldg(p1 + idx) - 0.5f;
                b = __ldg(p2 + idx) - 0.5f;
            }
        }
        unsigned pq[4];
        pq[0] = bcast_h2(a);
        pq[1] = bcast_h2(b);
        pq[2] = hfma2u(pq[0], pq[0], hmul2u(pq[1], pq[1]));  // ac^2+bc^2
        pq[3] = hmul2u(pq[0], pq[1]);                        // ac*bc

#pragma unroll
        for (int p = 0; p < NP; p++) {
            const int k = r - 2 * p;            // compile-time after unroll
            if (k >= 0 && k <= 11) {
                const int j = p % 6;
                if (k == 0) {
#pragma unroll
                    for (int q = 0; q < 4; q++)
                        acc[j][q] = hmul2u(pq[q], wk2(0));   // fresh pair (lane1 *0)
                } else {
#pragma unroll
                    for (int q = 0; q < 4; q++)
                        acc[j][q] = hfma2u(pq[q], wk2(k), acc[j][q]);
                }
            }
        }
        if (r >= 11 && ((r - 11) & 1) == 0) {
            const int p = (r - 11) >> 1;
            const int j = p % 6;
            uint4 w4 = make_uint4(acc[j][0], acc[j][1], acc[j][2], acc[j][3]);
            *reinterpret_cast<uint4*>(vw + p * PITCH + (tx + 5) * 4) = w4;
        }
    }
}

__global__ void __launch_bounds__(NTHREADS, 2)
ssim_main(const float* __restrict__ img1, const float* __restrict__ img2,
          float* __restrict__ out) {
    extern __shared__ unsigned vw[];      // [NP][PITCH]
    __shared__ float red[NTHREADS / 32];

    const int tx = threadIdx.x;
    const int y0 = blockIdx.x * TH;
    const int plane = blockIdx.y;

    const float* __restrict__ p1 = img1 + (size_t)plane * (IMG_W * IMG_H);
    const float* __restrict__ p2 = img2 + (size_t)plane * (IMG_W * IMG_H);

    // Boundary columns sx in {0..4} u {517..521}: exact constants.
    if (tx < 10) {
        const int sx = (tx < 5) ? tx : (tx + 512);
        const uint4 bc = make_uint4(HMU_BC, HMU_BC, HS_BC, HM_BC);
#pragma unroll
        for (int p = 0; p < NP; p++)
            *reinterpret_cast<uint4*>(vw + p * PITCH + sx * 4) = bc;
    }

    // ---------- Phase B ----------
    if (y0 >= 5 && y0 + TH + 5 <= IMG_H) vblur<true >(p1, p2, vw, y0, tx);
    else                                 vblur<false>(p1, p2, vw, y0, tx);
    __syncthreads();

    // ---------- Phase C: horizontal blur + SSIM epilogue (no guards) ----------
    const int rp  = tx & 7;       // pair-row 0..7 (output rows 2rp, 2rp+1)
    const int seg = tx >> 3;      // 0..63, exactly 8 output columns each
    const int c0  = seg * 8;

    unsigned acc[8][4];
    // smem col for output xout's tap k is (xout + k); window base = c0.
    const unsigned* rowp = vw + rp * PITCH + c0 * 4;

#pragma unroll
    for (int i = 0; i < 18; i++) {
        const uint4 w4 = *reinterpret_cast<const uint4*>(rowp + i * 4);
        unsigned pv[4] = {w4.x, w4.y, w4.z, w4.w};
#pragma unroll
        for (int xo = 0; xo < 8; xo++) {
            const int k = i - xo;
            if (k >= 0 && k <= 10) {
                if (k == 0) {
#pragma unroll
                    for (int q = 0; q < 4; q++)
                        acc[xo][q] = hmul2u(pv[q], wb2(0));
                } else {
#pragma unroll
                    for (int q = 0; q < 4; q++)
                        acc[xo][q] = hfma2u(pv[q], wb2(k < 6 ? k : 10 - k), acc[xo][q]);
                }
            }
        }
    }

    // h2 constants for the pair-packed epilogue
    const unsigned HC1   = bcast_h2(C1V);
    const unsigned HC2   = bcast_h2(C2V);
    const unsigned HTWO  = bcast_h2(2.0f);
    const unsigned HHALF = bcast_h2(0.5f);
    const unsigned HQTR  = bcast_h2(0.25f);
    const unsigned HHC1  = bcast_h2(0.5f + C1V);

    float lsum = 0.f;
#pragma unroll
    for (int xo = 0; xo < 8; xo++) {
        const unsigned mu1c = acc[xo][0];
        const unsigned mu2c = acc[xo][1];
        const unsigned epc  = acc[xo][2];
        const unsigned exc  = acc[xo][3];
        const unsigned msumc = hfma2u(mu1c, mu1c, hmul2u(mu2c, mu2c));
        const unsigned ssum  = hsub2u(epc, msumc);            // s1+s2
        const unsigned m12c  = hmul2u(mu1c, mu2c);
        const unsigned s12   = hsub2u(exc, m12c);
        // de-center: u = mu1c+mu2c; m12 = m12c + u/2 + 1/4;
        //            msum+C1 = msumc + u + (1/2+C1)
        const unsigned u      = hadd2u(mu1c, mu2c);
        const unsigned m12    = hadd2u(m12c, hfma2u(u, HHALF, HQTR));
        const unsigned msumC1 = hadd2u(msumc, hadd2u(u, HHC1));
        const unsigned numf1  = hfma2u(m12, HTWO, HC1);
        const unsigned numf2  = hfma2u(s12, HTWO, HC2);
        const unsigned num_h  = hmul2u(numf1, numf2);
        const unsigned ssumC2 = hadd2u(ssum, HC2);
        const unsigned den_h  = hmul2u(msumC1, ssumC2);
        const float2 numf = unpack_h2(num_h);
        const float2 denf = unpack_h2(den_h);
        lsum += __fdividef(numf.x, denf.x);
        lsum += __fdividef(numf.y, denf.y);
    }

    // ---------- reduction: shuffle -> smem -> one atomic per block ----------
#pragma unroll
    for (int off = 16; off > 0; off >>= 1)
        lsum += __shfl_xor_sync(0xffffffffu, lsum, off);
    if ((tx & 31) == 0) red[tx >> 5] = lsum;
    __syncthreads();

    if (tx == 0) {
        float bsum = 0.f;
#pragma unroll
        for (int w = 0; w < NTHREADS / 32; w++) bsum += red[w];
        atomicAdd(&g_accum, bsum);
        __threadfence();
        const unsigned int old = atomicAdd(&g_count, 1u);
        if (old == NBLOCKS - 1) {
            __threadfence();
            const float total = *(volatile float*)&g_accum;
            out[0] = 1.0f - total * (1.0f / NPIX);
            *(volatile float*)&g_accum = 0.f;
            *(volatile unsigned int*)&g_count = 0u;
        }
    }
}

extern "C" void kernel_launch(void* const* d_in, const int* in_sizes, int n_in,
                              void* d_out, int out_size) {
    const float* img1 = (const float*)d_in[0];
    const float* img2 = (const float*)d_in[1];

    const int smem = SMEM_WORDS * (int)sizeof(unsigned);   // 67,008 B
    cudaFuncSetAttribute(ssim_main, cudaFuncAttributeMaxDynamicSharedMemorySize, smem);

    dim3 grid(IMG_H / TH, PLANES);                          // (32, 96)
    ssim_main<<<grid, NTHREADS, smem>>>(img1, img2, (float*)d_out);
}